// round 3
// baseline (speedup 1.0000x reference)
#include <cuda_runtime.h>

#define HEADS 4
#define DIM   64
#define BB    8
#define QQ    128
#define VV    128
#define NN    (BB*QQ)   // 1024

// Scratch (device globals — no allocation allowed)
__device__ float2 g_QU[HEADS * NN * DIM];          // [h][n][j] complex
__device__ float2 g_VU[HEADS * BB * VV * DIM];     // [h][b][v][j] complex
__device__ float  g_acc[NN * HEADS * DIM];         // [n][h*64+j] real

// ---------------------------------------------------------------------------
// Kernel 1: QU[h,n,j] = q[n,:] @ U[h,0:64,j];  VU[h,b,v,j] = vals[b,v,:] @ U[h,64:128,j]
// ---------------------------------------------------------------------------
__global__ void __launch_bounds__(256) k_compute_u(
    const float* __restrict__ q,      // [1024,64]
    const float* __restrict__ vals,   // [1024,64] (b*V+v rows)
    const float* __restrict__ Ure,    // [4,128,64]
    const float* __restrict__ Uim)
{
    const int QU_TOT = HEADS * NN * DIM;   // 262144
    int idx = blockIdx.x * blockDim.x + threadIdx.x;
    if (idx < QU_TOT) {
        int j = idx & 63;
        int n = (idx >> 6) & (NN - 1);
        int h = idx >> 16;
        const float* xr = q + n * 64;
        const float* ur = Ure + h * 8192 + j;
        const float* ui = Uim + h * 8192 + j;
        float ar = 0.f, ai = 0.f;
        #pragma unroll 8
        for (int i = 0; i < 64; i++) {
            float xv = __ldg(xr + i);
            ar = fmaf(xv, __ldg(ur + i * 64), ar);
            ai = fmaf(xv, __ldg(ui + i * 64), ai);
        }
        g_QU[idx] = make_float2(ar, ai);
    } else {
        int t = idx - QU_TOT;
        if (t >= HEADS * BB * VV * DIM) return;
        int j  = t & 63;
        int bv = (t >> 6) & (BB * VV - 1);
        int h  = t >> 16;
        const float* xr = vals + bv * 64;
        const float* ur = Ure + h * 8192 + 4096 + j;   // rows 64..127
        const float* ui = Uim + h * 8192 + 4096 + j;
        float ar = 0.f, ai = 0.f;
        #pragma unroll 8
        for (int i = 0; i < 64; i++) {
            float xv = __ldg(xr + i);
            ar = fmaf(xv, __ldg(ur + i * 64), ar);
            ai = fmaf(xv, __ldg(ui + i * 64), ai);
        }
        g_VU[t] = make_float2(ar, ai);
    }
}

// ---------------------------------------------------------------------------
// Kernel 2: EUNN+modrelu recurrence. One warp per (h, n). Lane l owns complex
// elements 2l and 2l+1 of the 64-wide state.
// ---------------------------------------------------------------------------
__global__ void __launch_bounds__(256) k_recur(
    const float* __restrict__ bias,   // [4,64]
    const float* __restrict__ th1,    // [4,32]
    const float* __restrict__ ph1,    // [4,32]
    const float* __restrict__ th2,    // [4,31]
    const float* __restrict__ ph2,    // [4,31]
    const float* __restrict__ om)     // [4,64]
{
    const unsigned FULL = 0xffffffffu;
    int w = (blockIdx.x * blockDim.x + threadIdx.x) >> 5;   // 0..4095
    int l = threadIdx.x & 31;
    int h = w >> 10;
    int n = w & (NN - 1);
    int b = n >> 7;

    // Per-lane rotation constants
    float c1, s1, e1r, e1i;
    sincosf(th1[h * 32 + l], &s1, &c1);
    sincosf(ph1[h * 32 + l], &e1i, &e1r);

    float c2 = 1.f, s2 = 0.f, e2r = 1.f, e2i = 0.f;   // pair (2l+1, 2l+2): params index l
    if (l < 31) {
        sincosf(th2[h * 31 + l], &s2, &c2);
        sincosf(ph2[h * 31 + l], &e2i, &e2r);
    }
    float c2p = 1.f, s2p = 0.f;                        // my elem 2l is "b" output of pair l-1
    if (l > 0) {
        sincosf(th2[h * 31 + l - 1], &s2p, &c2p);
    }
    float eomAr, eomAi, eomBr, eomBi;
    sincosf(om[h * 64 + 2 * l],     &eomAi, &eomAr);
    sincosf(om[h * 64 + 2 * l + 1], &eomBi, &eomBr);
    float bA = bias[h * 64 + 2 * l];
    float bB = bias[h * 64 + 2 * l + 1];

    // Constant per-warp input term (QU), and per-step VU pointer
    const float4 qu = __ldg((const float4*)&g_QU[(h * NN + n) * DIM + 2 * l]);
    const float4* vup = (const float4*)&g_VU[((h * BB + b) * VV) * DIM + 2 * l];

    float Ar = 0.f, Ai = 0.f, Br = 0.f, Bi = 0.f;

    #pragma unroll 2
    for (int v = 0; v < VV; v++) {
        float4 vu = __ldg(vup); vup += DIM / 2;   // 32 float4 per step row

        // EUNN layer 1: pair (2l, 2l+1)
        float tAr = c1 * Ar - s1 * Br;
        float tAi = c1 * Ai - s1 * Bi;
        float nBr = s1 * Ar + c1 * Br;
        float nBi = s1 * Ai + c1 * Bi;
        float nAr = e1r * tAr - e1i * tAi;
        float nAi = e1r * tAi + e1i * tAr;

        // Cross-lane exchange for layer 2
        float xur = __shfl_up_sync(FULL, nBr, 1);     // nB of lane l-1
        float xui = __shfl_up_sync(FULL, nBi, 1);
        float xdr = __shfl_down_sync(FULL, nAr, 1);   // nA of lane l+1
        float xdi = __shfl_down_sync(FULL, nAi, 1);

        // layer 2: elem 2l+1 = e2*(c2*nB - s2*nA_next); elem 2l = s2p*nB_prev + c2p*nA
        float t2r = c2 * nBr - s2 * xdr;
        float t2i = c2 * nBi - s2 * xdi;
        float oBr = e2r * t2r - e2i * t2i;
        float oBi = e2r * t2i + e2i * t2r;
        float oAr = s2p * xur + c2p * nAr;
        float oAi = s2p * xui + c2p * nAi;

        // diagonal phase + input
        float zAr = eomAr * oAr - eomAi * oAi + qu.x + vu.x;
        float zAi = eomAr * oAi + eomAi * oAr + qu.y + vu.y;
        float zBr = eomBr * oBr - eomBi * oBi + qu.z + vu.z;
        float zBi = eomBr * oBi + eomBi * oBr + qu.w + vu.w;

        // modrelu
        float sA = zAr * zAr + zAi * zAi;
        float mA = sA * rsqrtf(sA + 1e-30f);          // = |z|, safely 0 at z=0
        float scA = __fdividef(fmaxf(mA + bA, 0.f), mA + 1e-5f);
        Ar = zAr * scA; Ai = zAi * scA;

        float sB = zBr * zBr + zBi * zBi;
        float mB = sB * rsqrtf(sB + 1e-30f);
        float scB = __fdividef(fmaxf(mB + bB, 0.f), mB + 1e-5f);
        Br = zBr * scB; Bi = zBi * scB;
    }

    // acc[n][h*64 + 2l .. 2l+1] = Re(h_T)
    float2* accp = (float2*)&g_acc[n * (HEADS * DIM) + h * DIM + 2 * l];
    *accp = make_float2(Ar, Br);
}

// ---------------------------------------------------------------------------
// Kernel 3: y = acc @ W + b   ([1024,256] @ [256,64])
// ---------------------------------------------------------------------------
__global__ void __launch_bounds__(256) k_proj(
    const float* __restrict__ W,    // [256,64]
    const float* __restrict__ bd,   // [64]
    float* __restrict__ out)        // [1024,64]
{
    int o = threadIdx.x & 63;
    int r = threadIdx.x >> 6;
    int n = blockIdx.x * 4 + r;
    const float* a = g_acc + n * 256;
    float s = __ldg(bd + o);
    #pragma unroll 8
    for (int k = 0; k < 256; k++)
        s = fmaf(__ldg(a + k), __ldg(W + k * 64 + o), s);
    out[n * 64 + o] = s;
}

// ---------------------------------------------------------------------------
extern "C" void kernel_launch(void* const* d_in, const int* in_sizes, int n_in,
                              void* d_out, int out_size)
{
    const float* queries = (const float*)d_in[0];
    const float* values  = (const float*)d_in[1];
    const float* U_re    = (const float*)d_in[2];
    const float* U_im    = (const float*)d_in[3];
    const float* bias    = (const float*)d_in[4];
    const float* theta1  = (const float*)d_in[5];
    const float* phi1    = (const float*)d_in[6];
    const float* theta2  = (const float*)d_in[7];
    const float* phi2    = (const float*)d_in[8];
    const float* omega   = (const float*)d_in[9];
    const float* W_dense = (const float*)d_in[10];
    const float* b_dense = (const float*)d_in[11];
    float* out = (float*)d_out;

    k_compute_u<<<2048, 256>>>(queries, values, U_re, U_im);
    k_recur<<<512, 256>>>(bias, theta1, phi1, theta2, phi2, omega);
    k_proj<<<256, 256>>>(W_dense, b_dense, out);
}